// round 16
// baseline (speedup 1.0000x reference)
#include <cuda_runtime.h>
#include <cuda_bf16.h>
#include <cstdint>
#include <math.h>

// Problem constants
#define LSEQ   4096
#define DEMB   256
#define HID    256          // per-direction hidden
#define G4H    1024         // 4*HID
#define NT     24
#define START_TAG 22
#define STOP_TAG  23
#define NEGINF (-1.0e6f)

// ---------------- scratch (device globals; no allocation allowed) ----------------
__device__ float g_xp[2][LSEQ * G4H];      // input projections per direction (scan order)
__device__ float g_lstm_out[LSEQ * 512];   // [t][0:256)=fwd h, [256:512)=bwd h (final order)
__device__ float g_feats[LSEQ * NT];

// ---------------- helpers ----------------
__device__ __forceinline__ uint32_t s2u(const void* p) {
    return (uint32_t)__cvta_generic_to_shared(p);
}
__device__ __forceinline__ void cluster_sync_() {
    asm volatile("barrier.cluster.arrive.aligned;" ::: "memory");
    asm volatile("barrier.cluster.wait.aligned;" ::: "memory");
}
__device__ __forceinline__ void mbar_init(uint32_t a, uint32_t cnt) {
    asm volatile("mbarrier.init.shared.b64 [%0], %1;" :: "r"(a), "r"(cnt) : "memory");
}
__device__ __forceinline__ void mbar_expect_tx(uint32_t a, uint32_t bytes) {
    asm volatile("mbarrier.arrive.expect_tx.shared.b64 _, [%0], %1;"
                 :: "r"(a), "r"(bytes) : "memory");
}
__device__ __forceinline__ void mbar_wait(uint32_t a, uint32_t parity) {
    asm volatile(
        "{\n\t"
        ".reg .pred P1;\n"
        "LW_%=:\n\t"
        "mbarrier.try_wait.parity.acquire.cta.shared::cta.b64 P1, [%0], %1, 0x989680;\n\t"
        "@P1 bra LD_%=;\n\t"
        "bra LW_%=;\n"
        "LD_%=:\n\t"
        "}"
        :: "r"(a), "r"(parity) : "memory");
}
__device__ __forceinline__ uint32_t mapa_(uint32_t a, uint32_t pc) {
    uint32_t r;
    asm("mapa.shared::cluster.u32 %0, %1, %2;" : "=r"(r) : "r"(a), "r"(pc));
    return r;
}
__device__ __forceinline__ void st_async_tx(uint32_t raddr, float v, uint32_t rbar) {
    asm volatile("st.async.shared::cluster.mbarrier::complete_tx::bytes.b32 [%0], %1, [%2];"
                 :: "r"(raddr), "r"(__float_as_uint(v)), "r"(rbar) : "memory");
}
// fast, branch-free activations (__expf saturates cleanly at +-inf)
__device__ __forceinline__ float fsig(float x) {
    return __fdividef(1.0f, 1.0f + __expf(-x));
}
__device__ __forceinline__ float ftanh_(float x) {
    return 1.0f - __fdividef(2.0f, __expf(2.0f * x) + 1.0f);
}

// ---------------- kernel 1: embedding gather + input projection ----------------
__global__ __launch_bounds__(1024, 1)
void proj_kernel(const int* __restrict__ sent, const float* __restrict__ emb,
                 const float* __restrict__ Wf, const float* __restrict__ bihf,
                 const float* __restrict__ bhhf,
                 const float* __restrict__ Wb, const float* __restrict__ bihb,
                 const float* __restrict__ bhhb)
{
    __shared__ float4 xs[8][64];     // 8 timesteps x 256 floats
    const int dir = blockIdx.y;
    const int t0  = blockIdx.x * 8;
    const int tid = threadIdx.x;

    if (tid < 512) {
        int tt = tid >> 6, k4 = tid & 63;
        int s  = t0 + tt;
        int tok = sent[dir ? (LSEQ - 1 - s) : s];
        xs[tt][k4] = ((const float4*)emb)[(size_t)tok * 64 + k4];
    }
    __syncthreads();

    const float* W = dir ? Wb : Wf;
    const int row = tid;
    const float bias = dir ? (bihb[row] + bhhb[row]) : (bihf[row] + bhhf[row]);
    float acc[8];
#pragma unroll
    for (int i = 0; i < 8; i++) acc[i] = bias;

    const float4* W4 = (const float4*)(W + (size_t)row * DEMB);
#pragma unroll 8
    for (int k4 = 0; k4 < 64; k4++) {
        float4 w4 = __ldg(&W4[k4]);
#pragma unroll
        for (int tt = 0; tt < 8; tt++) {
            float4 x4 = xs[tt][k4];
            acc[tt] += w4.x * x4.x + w4.y * x4.y + w4.z * x4.z + w4.w * x4.w;
        }
    }
    float* out = g_xp[dir];
#pragma unroll
    for (int tt = 0; tt < 8; tt++)
        out[(size_t)(t0 + tt) * G4H + row] = acc[tt];
}

// ---------------- kernel 2a: LSTM recurrence, 16-CTA cluster version ----------------
// 2 clusters x 16 CTAs (runtime nonportable cluster). Each CTA owns 16 h-elems.
// Thread layout: row = tid>>3 (64 local gate rows = 4 gates x 16), ks = tid&7
// (32-K slice). Dot = 16 FFMA2/thread + 3-level shfl reduce within 8-lane groups.
// Same R10 protocol: double-buffered hb, st.async.b32 fills, 1024B expect_tx
// (16 CTAs x 16 values x 4B), re-arm immediately after the wait.
__global__ __launch_bounds__(512, 1)
void lstm16_kernel(const float* __restrict__ h0, const float* __restrict__ c0,
                   const float* __restrict__ Whh_f, const float* __restrict__ Whh_b)
{
    __shared__ __align__(16) float hb[2][HID];
    __shared__ float part[2][64];
    __shared__ __align__(8) unsigned long long mb_full[2];

    const int tid = threadIdx.x;
    uint32_t rank;
    asm("mov.u32 %0, %%cluster_ctarank;" : "=r"(rank));
    const int dir = blockIdx.x >> 4;

    const float* Whh = dir ? Whh_b : Whh_f;
    const float* xp  = g_xp[dir];

    const int row  = tid >> 3;           // 0..63 local gate row
    const int ks   = tid & 7;            // K slice (32 wide)
    const int g    = row >> 4;
    const int jr   = row & 15;
    const int grow = g * 256 + (int)rank * 16 + jr;   // global gate row
    const int k0   = ks * 32;

    // 32 K-values per thread = 16 packed f32x2 (k0*4 = 128B-aligned)
    unsigned long long w2[16];
    const unsigned long long* wrow =
        (const unsigned long long*)(Whh + (size_t)grow * HID + k0);
#pragma unroll
    for (int kk = 0; kk < 16; kk++) w2[kk] = __ldg(&wrow[kk]);

    const uint32_t fb0 = s2u(&mb_full[0]);
    const uint32_t fb1 = s2u(&mb_full[1]);

    if (tid == 0) {
        mbar_init(fb0, 1);
        mbar_init(fb1, 1);
        mbar_expect_tx(fb0, 1024);   // phase 0: h0 fill
        mbar_expect_tx(fb1, 1024);   // phase 0: t=0 producer fill
    }
    __syncthreads();
    cluster_sync_();

    float c = 0.0f;
    float xpv[4] = {0.f, 0.f, 0.f, 0.f};
    if (tid < 16) {
        c = c0[dir * HID + rank * 16 + tid];
        float h0v = h0[dir * HID + rank * 16 + tid];
#pragma unroll
        for (int gg = 0; gg < 4; gg++)
            xpv[gg] = xp[gg * 256 + rank * 16 + tid];
        uint32_t lslot = s2u(&hb[0][rank * 16 + tid]);
#pragma unroll
        for (int pc = 0; pc < 16; pc++)
            st_async_tx(mapa_(lslot, (uint32_t)pc), h0v, mapa_(fb0, (uint32_t)pc));
    }

    uint32_t phF0 = 0, phF1 = 0;
    int p = 0;
    for (int t = 0; t < LSEQ; t++) {
        if (p == 0) {
            mbar_wait(fb0, phF0); phF0 ^= 1;
            if (tid == 0) mbar_expect_tx(fb0, 1024);
        } else {
            mbar_wait(fb1, phF1); phF1 ^= 1;
            if (tid == 0) mbar_expect_tx(fb1, 1024);
        }

        float xpn[4] = {0.f, 0.f, 0.f, 0.f};
        if (tid < 16 && t + 1 < LSEQ) {
#pragma unroll
            for (int gg = 0; gg < 4; gg++)
                xpn[gg] = __ldg(&xp[(size_t)(t + 1) * G4H + gg * 256 + rank * 16 + tid]);
        }

        // 32-wide K-slice dot via packed f32x2 FMA
        const ulonglong2* h8 = (const ulonglong2*)&hb[p][k0];
        unsigned long long a0 = 0ull, a1 = 0ull;
#pragma unroll
        for (int q = 0; q < 8; q++) {
            ulonglong2 hv = h8[q];
            asm("fma.rn.f32x2 %0, %1, %2, %0;" : "+l"(a0) : "l"(w2[2 * q]),     "l"(hv.x));
            asm("fma.rn.f32x2 %0, %1, %2, %0;" : "+l"(a1) : "l"(w2[2 * q + 1]), "l"(hv.y));
        }
        asm("add.rn.f32x2 %0, %1, %2;" : "=l"(a0) : "l"(a0), "l"(a1));
        uint32_t alo, ahi;
        asm("mov.b64 {%0,%1}, %2;" : "=r"(alo), "=r"(ahi) : "l"(a0));
        float s = __uint_as_float(alo) + __uint_as_float(ahi);
        // reduce over 8 K-slices (within 8-lane group)
        s += __shfl_down_sync(0xffffffffu, s, 4);
        s += __shfl_down_sync(0xffffffffu, s, 2);
        s += __shfl_down_sync(0xffffffffu, s, 1);
        if (ks == 0) part[p][row] = s;
        __syncthreads();      // part[p] ready; all local reads of hb[p] retired

        if (tid < 16) {
            const int jj = tid;
            float gv[4];
#pragma unroll
            for (int gg = 0; gg < 4; gg++)
                gv[gg] = xpv[gg] + part[p][gg * 16 + jj];

            float ii  = fsig(gv[0]);
            float ff  = fsig(gv[1]);
            float ggt = ftanh_(gv[2]);
            float oo  = fsig(gv[3]);
            c = ff * c + ii * ggt;
            float hj = oo * ftanh_(c);

            int tt = dir ? (LSEQ - 1 - t) : t;
            g_lstm_out[(size_t)tt * 512 + dir * 256 + rank * 16 + jj] = hj;

            if (t + 1 < LSEQ) {
                uint32_t lslot = s2u(&hb[p ^ 1][rank * 16 + jj]);
                uint32_t fbn   = (p == 0) ? fb1 : fb0;
#pragma unroll
                for (int pc = 0; pc < 16; pc++)
                    st_async_tx(mapa_(lslot, (uint32_t)pc), hj, mapa_(fbn, (uint32_t)pc));
            }
#pragma unroll
            for (int gg = 0; gg < 4; gg++) xpv[gg] = xpn[gg];
        }
        p ^= 1;
    }
}

// ---------------- kernel 2b: LSTM recurrence, byte-exact R10 8-CTA fallback ----------------
__global__ __launch_bounds__(512, 1) __cluster_dims__(8, 1, 1)
void lstm_kernel(const float* __restrict__ h0, const float* __restrict__ c0,
                 const float* __restrict__ Whh_f, const float* __restrict__ Whh_b)
{
    __shared__ __align__(16) float hb[2][HID];
    __shared__ float part[2][4][128];
    __shared__ __align__(8) unsigned long long mb_full[2];

    const int tid = threadIdx.x;
    uint32_t rank;
    asm("mov.u32 %0, %%cluster_ctarank;" : "=r"(rank));
    const int dir = blockIdx.x >> 3;

    const float* Whh = dir ? Whh_b : Whh_f;
    const float* xp  = g_xp[dir];

    const int lr = tid & 127;
    const int kq = tid >> 7;
    const int g  = lr >> 5;
    const int j  = lr & 31;
    const int grow = g * 256 + (int)rank * 32 + j;
    const int k0   = kq * 64;

    unsigned long long w2[32];
    const unsigned long long* wrow =
        (const unsigned long long*)(Whh + (size_t)grow * HID + k0);
#pragma unroll
    for (int kk = 0; kk < 32; kk++) w2[kk] = __ldg(&wrow[kk]);

    const uint32_t fb0 = s2u(&mb_full[0]);
    const uint32_t fb1 = s2u(&mb_full[1]);

    if (tid == 0) {
        mbar_init(fb0, 1);
        mbar_init(fb1, 1);
        mbar_expect_tx(fb0, 1024);
        mbar_expect_tx(fb1, 1024);
    }
    __syncthreads();
    cluster_sync_();

    float c = 0.0f;
    float xpv[4] = {0.f, 0.f, 0.f, 0.f};
    if (tid < 32) {
        c = c0[dir * HID + rank * 32 + tid];
        float h0v = h0[dir * HID + rank * 32 + tid];
#pragma unroll
        for (int gg = 0; gg < 4; gg++)
            xpv[gg] = xp[gg * 256 + rank * 32 + tid];
        uint32_t lslot = s2u(&hb[0][rank * 32 + tid]);
#pragma unroll
        for (int pc = 0; pc < 8; pc++)
            st_async_tx(mapa_(lslot, pc), h0v, mapa_(fb0, pc));
    }

    uint32_t phF0 = 0, phF1 = 0;
    int p = 0;
    for (int t = 0; t < LSEQ; t++) {
        if (p == 0) {
            mbar_wait(fb0, phF0); phF0 ^= 1;
            if (tid == 0) mbar_expect_tx(fb0, 1024);
        } else {
            mbar_wait(fb1, phF1); phF1 ^= 1;
            if (tid == 0) mbar_expect_tx(fb1, 1024);
        }

        float xpn[4] = {0.f, 0.f, 0.f, 0.f};
        if (tid < 32 && t + 1 < LSEQ) {
#pragma unroll
            for (int gg = 0; gg < 4; gg++)
                xpn[gg] = __ldg(&xp[(size_t)(t + 1) * G4H + gg * 256 + rank * 32 + tid]);
        }

        const ulonglong2* h8 = (const ulonglong2*)&hb[p][k0];
        unsigned long long a0 = 0ull, a1 = 0ull;
#pragma unroll
        for (int q = 0; q < 16; q++) {
            ulonglong2 hv = h8[q];
            asm("fma.rn.f32x2 %0, %1, %2, %0;" : "+l"(a0) : "l"(w2[2 * q]),     "l"(hv.x));
            asm("fma.rn.f32x2 %0, %1, %2, %0;" : "+l"(a1) : "l"(w2[2 * q + 1]), "l"(hv.y));
        }
        asm("add.rn.f32x2 %0, %1, %2;" : "=l"(a0) : "l"(a0), "l"(a1));
        uint32_t alo, ahi;
        asm("mov.b64 {%0,%1}, %2;" : "=r"(alo), "=r"(ahi) : "l"(a0));
        part[p][kq][lr] = __uint_as_float(alo) + __uint_as_float(ahi);
        __syncthreads();

        if (tid < 32) {
            const int jj = tid;
            float gv[4];
#pragma unroll
            for (int gg = 0; gg < 4; gg++) {
                float s = part[p][0][gg * 32 + jj] + part[p][1][gg * 32 + jj]
                        + part[p][2][gg * 32 + jj] + part[p][3][gg * 32 + jj];
                gv[gg] = xpv[gg] + s;
            }
            float ii  = fsig(gv[0]);
            float ff  = fsig(gv[1]);
            float ggt = ftanh_(gv[2]);
            float oo  = fsig(gv[3]);
            c = ff * c + ii * ggt;
            float hj = oo * ftanh_(c);

            int tt = dir ? (LSEQ - 1 - t) : t;
            g_lstm_out[(size_t)tt * 512 + dir * 256 + rank * 32 + jj] = hj;

            if (t + 1 < LSEQ) {
                uint32_t lslot = s2u(&hb[p ^ 1][rank * 32 + jj]);
                uint32_t fbn   = (p == 0) ? fb1 : fb0;
#pragma unroll
                for (int pc = 0; pc < 8; pc++)
                    st_async_tx(mapa_(lslot, pc), hj, mapa_(fbn, pc));
            }
#pragma unroll
            for (int gg = 0; gg < 4; gg++) xpv[gg] = xpn[gg];
        }
        p ^= 1;
    }
}

// ---------------- kernel 3: feats = lstm_out @ W_out^T + b_out ----------------
__global__ __launch_bounds__(256, 4)
void feats_kernel(const float* __restrict__ Wout, const float* __restrict__ bout)
{
    int gw   = (blockIdx.x * blockDim.x + threadIdx.x) >> 5;
    int lane = threadIdx.x & 31;
    if (gw >= LSEQ * NT) return;
    int t = gw / NT, n = gw % NT;

    const float4* xr = (const float4*)(g_lstm_out + (size_t)t * 512);
    const float4* wr = (const float4*)(Wout + (size_t)n * 512);
    float acc = 0.0f;
#pragma unroll
    for (int q = 0; q < 4; q++) {
        float4 a = xr[q * 32 + lane];
        float4 b = __ldg(&wr[q * 32 + lane]);
        acc += a.x * b.x + a.y * b.y + a.z * b.z + a.w * b.w;
    }
#pragma unroll
    for (int off = 16; off; off >>= 1)
        acc += __shfl_down_sync(0xffffffffu, acc, off);
    if (lane == 0) g_feats[t * NT + n] = acc + bout[n];
}

// ---------------- kernel 4: Viterbi (R10 version — measured 789us, best known) ----------------
#define BP_BYTES   (LSEQ * NT)               // 98304
#define FCH_BYTES  (256 * NT * 4)            // 24576
#define PATH_BYTES (LSEQ * 4)                // 16384
#define VSMEM      (BP_BYTES + FCH_BYTES + PATH_BYTES + 128)

// combine keeping 'a' (lower index range) on ties -> jnp.argmax first-max
__device__ __forceinline__ void amax2_(float& v, int& i, float v2, int i2) {
    bool ge = (v >= v2);
    v = ge ? v : v2;
    i = ge ? i : i2;
}

__global__ void viterbi_kernel(const float* __restrict__ trans,
                               float* __restrict__ out, int out_size)
{
    extern __shared__ char sm[];
    unsigned char* bp   = (unsigned char*)sm;
    float*         fch  = (float*)(sm + BP_BYTES);
    int*           path = (int*)(sm + BP_BYTES + FCH_BYTES);
    __shared__ float score_s;

    const int tid = threadIdx.x;

    float fvr = (tid == START_TAG) ? 0.0f : NEGINF;
    float trow[NT];
    if (tid < NT) {
#pragma unroll
        for (int p_ = 0; p_ < NT; p_++) trow[p_] = trans[tid * NT + p_];
    } else {
#pragma unroll
        for (int p_ = 0; p_ < NT; p_++) trow[p_] = 0.0f;
    }
    __syncthreads();

    for (int ch = 0; ch < LSEQ / 256; ch++) {
        const float* src = g_feats + (size_t)ch * 256 * NT;
        for (int i = tid; i < 256 * NT; i += blockDim.x) fch[i] = src[i];
        __syncthreads();

        if (tid < 32) {
            for (int s = 0; s < 256; s++) {
                int t = ch * 256 + s;
                float sc[32];
#pragma unroll
                for (int k = 0; k < NT; k++)
                    sc[k] = __shfl_sync(0xffffffffu, fvr, k) + trow[k];
#pragma unroll
                for (int k = NT; k < 32; k++) sc[k] = -3.4e38f;

                float v[16]; int ix[16];
#pragma unroll
                for (int m = 0; m < 16; m++) {
                    bool ge = (sc[2 * m] >= sc[2 * m + 1]);
                    v[m]  = ge ? sc[2 * m] : sc[2 * m + 1];
                    ix[m] = ge ? (2 * m) : (2 * m + 1);
                }
#pragma unroll
                for (int m = 0; m < 8; m++) amax2_(v[m], ix[m], v[m + 8], ix[m + 8]);
#pragma unroll
                for (int m = 0; m < 4; m++) amax2_(v[m], ix[m], v[m + 4], ix[m + 4]);
#pragma unroll
                for (int m = 0; m < 2; m++) amax2_(v[m], ix[m], v[m + 2], ix[m + 2]);
                amax2_(v[0], ix[0], v[1], ix[1]);

                float fval = (tid < NT) ? fch[s * NT + tid] : 0.0f;
                fvr = v[0] + fval;
                if (tid < NT) bp[t * NT + tid] = (unsigned char)ix[0];
            }
        }
        __syncthreads();
    }

    if (tid < 32) {
        float sc[32];
#pragma unroll
        for (int k = 0; k < NT; k++)
            sc[k] = __shfl_sync(0xffffffffu, fvr, k) + __ldg(&trans[STOP_TAG * NT + k]);
#pragma unroll
        for (int k = NT; k < 32; k++) sc[k] = -3.4e38f;
        float v[16]; int ix[16];
#pragma unroll
        for (int m = 0; m < 16; m++) {
            bool ge = (sc[2 * m] >= sc[2 * m + 1]);
            v[m]  = ge ? sc[2 * m] : sc[2 * m + 1];
            ix[m] = ge ? (2 * m) : (2 * m + 1);
        }
#pragma unroll
        for (int m = 0; m < 8; m++) amax2_(v[m], ix[m], v[m + 8], ix[m + 8]);
#pragma unroll
        for (int m = 0; m < 4; m++) amax2_(v[m], ix[m], v[m + 4], ix[m + 4]);
#pragma unroll
        for (int m = 0; m < 2; m++) amax2_(v[m], ix[m], v[m + 2], ix[m + 2]);
        amax2_(v[0], ix[0], v[1], ix[1]);

        if (tid == 0) {
            score_s = v[0];
            int tag = ix[0];
            for (int t = LSEQ - 1; t >= 0; t--) {
                path[t] = tag;
                tag = bp[t * NT + tag];
            }
        }
    }
    __syncthreads();

    if (out_size >= LSEQ + 1) {
        if (tid == 0) out[0] = score_s;
        for (int t = tid; t < LSEQ; t += blockDim.x) out[1 + t] = (float)path[t];
    } else if (out_size >= LSEQ) {
        for (int t = tid; t < LSEQ; t += blockDim.x) out[t] = (float)path[t];
    } else if (out_size >= 1) {
        if (tid == 0) out[0] = score_s;
    }
}

// ---------------- launch ----------------
extern "C" void kernel_launch(void* const* d_in, const int* in_sizes, int n_in,
                              void* d_out, int out_size)
{
    const int*   sent  = (const int*)d_in[0];
    const float* h0    = (const float*)d_in[1];
    const float* c0    = (const float*)d_in[2];
    const float* emb   = (const float*)d_in[3];
    const float* Wihf  = (const float*)d_in[4];
    const float* Whhf  = (const float*)d_in[5];
    const float* bihf  = (const float*)d_in[6];
    const float* bhhf  = (const float*)d_in[7];
    const float* Wihb  = (const float*)d_in[8];
    const float* Whhb  = (const float*)d_in[9];
    const float* bihb  = (const float*)d_in[10];
    const float* bhhb  = (const float*)d_in[11];
    const float* Wout  = (const float*)d_in[12];
    const float* bout  = (const float*)d_in[13];
    const float* trans = (const float*)d_in[14];

    cudaFuncSetAttribute(viterbi_kernel,
                         cudaFuncAttributeMaxDynamicSharedMemorySize, VSMEM);

    proj_kernel<<<dim3(LSEQ / 8, 2), 1024>>>(sent, emb, Wihf, bihf, bhhf,
                                             Wihb, bihb, bhhb);

    // ---- LSTM: try 16-CTA nonportable cluster; fall back to proven 8-CTA ----
    // Deterministic: identical host calls on every invocation, no cached state.
    bool did16 = false;
    cudaError_t ea = cudaFuncSetAttribute(
        lstm16_kernel, cudaFuncAttributeNonPortableClusterSizeAllowed, 1);
    if (ea == cudaSuccess) {
        cudaLaunchConfig_t cfg = {};
        cfg.gridDim  = dim3(32, 1, 1);
        cfg.blockDim = dim3(512, 1, 1);
        cfg.dynamicSmemBytes = 0;
        cfg.stream = 0;
        int maxC = 0;
        cudaError_t eo = cudaOccupancyMaxPotentialClusterSize(&maxC, lstm16_kernel, &cfg);
        if (eo == cudaSuccess && maxC >= 16) {
            cudaLaunchAttribute attrs[1];
            attrs[0].id = cudaLaunchAttributeClusterDimension;
            attrs[0].val.clusterDim.x = 16;
            attrs[0].val.clusterDim.y = 1;
            attrs[0].val.clusterDim.z = 1;
            cfg.attrs = attrs;
            cfg.numAttrs = 1;
            cudaError_t el = cudaLaunchKernelEx(&cfg, lstm16_kernel,
                                                h0, c0, Whhf, Whhb);
            did16 = (el == cudaSuccess);
        }
    }
    if (!did16) {
        lstm_kernel<<<16, 512>>>(h0, c0, Whhf, Whhb);
    }

    int nwarps  = LSEQ * NT;
    int nblocks = (nwarps * 32 + 255) / 256;
    feats_kernel<<<nblocks, 256>>>(Wout, bout);

    viterbi_kernel<<<1, 128, VSMEM>>>(trans, (float*)d_out, out_size);
}

// round 17
// speedup vs baseline: 2.8736x; 2.8736x over previous
#include <cuda_runtime.h>
#include <cuda_bf16.h>
#include <cstdint>
#include <math.h>

// Problem constants
#define LSEQ   4096
#define DEMB   256
#define HID    256          // per-direction hidden
#define G4H    1024         // 4*HID
#define NT     24
#define START_TAG 22
#define STOP_TAG  23
#define NEGINF (-1.0e6f)

// ---------------- scratch (device globals; no allocation allowed) ----------------
__device__ float g_xp[2][LSEQ * G4H];      // input projections per direction (scan order)
__device__ float g_lstm_out[LSEQ * 512];   // [t][0:256)=fwd h, [256:512)=bwd h (final order)
__device__ float g_feats[LSEQ * NT];

// ---------------- helpers ----------------
__device__ __forceinline__ uint32_t s2u(const void* p) {
    return (uint32_t)__cvta_generic_to_shared(p);
}
__device__ __forceinline__ void cluster_sync_() {
    asm volatile("barrier.cluster.arrive.aligned;" ::: "memory");
    asm volatile("barrier.cluster.wait.aligned;" ::: "memory");
}
__device__ __forceinline__ void mbar_init(uint32_t a, uint32_t cnt) {
    asm volatile("mbarrier.init.shared.b64 [%0], %1;" :: "r"(a), "r"(cnt) : "memory");
}
__device__ __forceinline__ void mbar_expect_tx(uint32_t a, uint32_t bytes) {
    asm volatile("mbarrier.arrive.expect_tx.shared.b64 _, [%0], %1;"
                 :: "r"(a), "r"(bytes) : "memory");
}
__device__ __forceinline__ void mbar_wait(uint32_t a, uint32_t parity) {
    asm volatile(
        "{\n\t"
        ".reg .pred P1;\n"
        "LW_%=:\n\t"
        "mbarrier.try_wait.parity.acquire.cta.shared::cta.b64 P1, [%0], %1, 0x989680;\n\t"
        "@P1 bra LD_%=;\n\t"
        "bra LW_%=;\n"
        "LD_%=:\n\t"
        "}"
        :: "r"(a), "r"(parity) : "memory");
}
__device__ __forceinline__ uint32_t mapa_(uint32_t a, uint32_t pc) {
    uint32_t r;
    asm("mapa.shared::cluster.u32 %0, %1, %2;" : "=r"(r) : "r"(a), "r"(pc));
    return r;
}
__device__ __forceinline__ void st_async_tx(uint32_t raddr, float v, uint32_t rbar) {
    asm volatile("st.async.shared::cluster.mbarrier::complete_tx::bytes.b32 [%0], %1, [%2];"
                 :: "r"(raddr), "r"(__float_as_uint(v)), "r"(rbar) : "memory");
}
// fast, branch-free activations (__expf saturates cleanly at +-inf)
__device__ __forceinline__ float fsig(float x) {
    return __fdividef(1.0f, 1.0f + __expf(-x));
}
__device__ __forceinline__ float ftanh_(float x) {
    return 1.0f - __fdividef(2.0f, __expf(2.0f * x) + 1.0f);
}

// ---------------- kernel 1: embedding gather + input projection ----------------
__global__ __launch_bounds__(1024, 1)
void proj_kernel(const int* __restrict__ sent, const float* __restrict__ emb,
                 const float* __restrict__ Wf, const float* __restrict__ bihf,
                 const float* __restrict__ bhhf,
                 const float* __restrict__ Wb, const float* __restrict__ bihb,
                 const float* __restrict__ bhhb)
{
    __shared__ float4 xs[8][64];     // 8 timesteps x 256 floats
    const int dir = blockIdx.y;
    const int t0  = blockIdx.x * 8;
    const int tid = threadIdx.x;

    if (tid < 512) {
        int tt = tid >> 6, k4 = tid & 63;
        int s  = t0 + tt;
        int tok = sent[dir ? (LSEQ - 1 - s) : s];
        xs[tt][k4] = ((const float4*)emb)[(size_t)tok * 64 + k4];
    }
    __syncthreads();

    const float* W = dir ? Wb : Wf;
    const int row = tid;
    const float bias = dir ? (bihb[row] + bhhb[row]) : (bihf[row] + bhhf[row]);
    float acc[8];
#pragma unroll
    for (int i = 0; i < 8; i++) acc[i] = bias;

    const float4* W4 = (const float4*)(W + (size_t)row * DEMB);
#pragma unroll 8
    for (int k4 = 0; k4 < 64; k4++) {
        float4 w4 = __ldg(&W4[k4]);
#pragma unroll
        for (int tt = 0; tt < 8; tt++) {
            float4 x4 = xs[tt][k4];
            acc[tt] += w4.x * x4.x + w4.y * x4.y + w4.z * x4.z + w4.w * x4.w;
        }
    }
    float* out = g_xp[dir];
#pragma unroll
    for (int tt = 0; tt < 8; tt++)
        out[(size_t)(t0 + tt) * G4H + row] = acc[tt];
}

// ---------------- kernel 2: the sequential LSTM recurrence ----------------
// R10 protocol verbatim (8-CTA clusters, st.async.b32 x 256/phase, 1024B
// expect_tx, re-arm immediately after the wait — proof in R10 notes).
// Three micro-trims vs R10, all off the transport/barrier/MUFU structure:
//  (1) peer addresses mapa'd ONCE pre-loop; in-loop sends use +imm offsets
//      (hb[1] = hb[0]+1024B, fb1 = fb0+8B within the peer window)
//  (2) 4-accumulator dot: FFMA2 chains of 8 (latency 32) instead of 16
//  (3) in-loop STG moved to warp 1: it stores output(t-1) from its own slice
//      of hb[p], read BEFORE its BAR_mid arrival (so the overwrite-gating
//      proof covers it: peer overwrites of hb[p] at t+1 are gated on our
//      tail's step-t sends, which follow BAR_mid, which warp 1 only arrives
//      at after its read). Tail stores only the final step after the loop.
__global__ __launch_bounds__(512, 1) __cluster_dims__(8, 1, 1)
void lstm_kernel(const float* __restrict__ h0, const float* __restrict__ c0,
                 const float* __restrict__ Whh_f, const float* __restrict__ Whh_b)
{
    __shared__ __align__(16) float hb[2][HID];
    __shared__ float part[2][4][128];
    __shared__ __align__(8) unsigned long long mb_full[2];

    const int tid = threadIdx.x;
    uint32_t rank;
    asm("mov.u32 %0, %%cluster_ctarank;" : "=r"(rank));
    const int dir = blockIdx.x >> 3;

    const float* Whh = dir ? Whh_b : Whh_f;
    const float* xp  = g_xp[dir];

    const int lr = tid & 127;
    const int kq = tid >> 7;
    const int g  = lr >> 5;
    const int j  = lr & 31;
    const int grow = g * 256 + (int)rank * 32 + j;   // global gate row
    const int k0   = kq * 64;

    // W_hh slice as 32 packed f32x2 pairs (row is 1024B-aligned; k0*4 is 256B-aligned)
    unsigned long long w2[32];
    const unsigned long long* wrow =
        (const unsigned long long*)(Whh + (size_t)grow * HID + k0);
#pragma unroll
    for (int kk = 0; kk < 32; kk++) w2[kk] = __ldg(&wrow[kk]);

    const uint32_t fb0 = s2u(&mb_full[0]);
    const uint32_t fb1 = s2u(&mb_full[1]);

    // (1) precompute peer addresses once (tail lanes only use them, but
    // computing in all lanes keeps control flow uniform)
    uint32_t slot0[8], bar0[8];
    {
        uint32_t lslot = s2u(&hb[0][rank * 32 + (tid & 31)]);
#pragma unroll
        for (int pc = 0; pc < 8; pc++) {
            slot0[pc] = mapa_(lslot, (uint32_t)pc);   // peer &hb[0][our slot]
            bar0[pc]  = mapa_(fb0,   (uint32_t)pc);   // peer fb0
        }
    }

    // init + arm BEFORE cluster_sync so no tx can hit an un-armed barrier
    if (tid == 0) {
        mbar_init(fb0, 1);
        mbar_init(fb1, 1);
        mbar_expect_tx(fb0, 1024);   // phase 0: h0 fill
        mbar_expect_tx(fb1, 1024);   // phase 0: t=0 producer fill
    }
    __syncthreads();
    cluster_sync_();

    float c = 0.0f;
    float hj = 0.0f;
    float xpv[4] = {0.f, 0.f, 0.f, 0.f};
    if (tid < 32) {
        c = c0[dir * HID + rank * 32 + tid];
        float h0v = h0[dir * HID + rank * 32 + tid];
#pragma unroll
        for (int gg = 0; gg < 4; gg++)
            xpv[gg] = xp[gg * 256 + rank * 32 + tid];
        // broadcast h0 slice to hb[0] of all 8 CTAs (incl self), tx -> full[0]
#pragma unroll
        for (int pc = 0; pc < 8; pc++)
            st_async_tx(slot0[pc], h0v, bar0[pc]);
    }

    uint32_t phF0 = 0, phF1 = 0;
    int p = 0;
    for (int t = 0; t < LSEQ; t++) {
        // wait h(t) in hb[p], then re-arm the SAME barrier (R10 proof)
        if (p == 0) {
            mbar_wait(fb0, phF0); phF0 ^= 1;
            if (tid == 0) mbar_expect_tx(fb0, 1024);
        } else {
            mbar_wait(fb1, phF1); phF1 ^= 1;
            if (tid == 0) mbar_expect_tx(fb1, 1024);
        }

        // prefetch next step's xp rows (hidden behind this step's dot compute)
        float xpn[4] = {0.f, 0.f, 0.f, 0.f};
        if (tid < 32 && t + 1 < LSEQ) {
#pragma unroll
            for (int gg = 0; gg < 4; gg++)
                xpn[gg] = __ldg(&xp[(size_t)(t + 1) * G4H + gg * 256 + rank * 32 + tid]);
        }

        // (2) partial dot: 4 accumulator chains of 8 FFMA2 each
        const ulonglong2* h8 = (const ulonglong2*)&hb[p][k0];
        unsigned long long a0 = 0ull, a1 = 0ull, a2 = 0ull, a3 = 0ull;
#pragma unroll
        for (int q = 0; q < 8; q++) {
            ulonglong2 hva = h8[2 * q];
            ulonglong2 hvb = h8[2 * q + 1];
            asm("fma.rn.f32x2 %0, %1, %2, %0;" : "+l"(a0) : "l"(w2[4 * q]),     "l"(hva.x));
            asm("fma.rn.f32x2 %0, %1, %2, %0;" : "+l"(a1) : "l"(w2[4 * q + 1]), "l"(hva.y));
            asm("fma.rn.f32x2 %0, %1, %2, %0;" : "+l"(a2) : "l"(w2[4 * q + 2]), "l"(hvb.x));
            asm("fma.rn.f32x2 %0, %1, %2, %0;" : "+l"(a3) : "l"(w2[4 * q + 3]), "l"(hvb.y));
        }
        asm("add.rn.f32x2 %0, %1, %2;" : "=l"(a0) : "l"(a0), "l"(a2));
        asm("add.rn.f32x2 %0, %1, %2;" : "=l"(a1) : "l"(a1), "l"(a3));
        asm("add.rn.f32x2 %0, %1, %2;" : "=l"(a0) : "l"(a0), "l"(a1));
        uint32_t alo, ahi;
        asm("mov.b64 {%0,%1}, %2;" : "=r"(alo), "=r"(ahi) : "l"(a0));
        part[p][kq][lr] = __uint_as_float(alo) + __uint_as_float(ahi);

        // (3) warp 1 stores output(t-1) from hb[p] BEFORE its barrier arrival
        if (t > 0 && tid >= 32 && tid < 64) {
            int lane = tid - 32;
            float hprev = hb[p][rank * 32 + lane];
            int tprev = dir ? (LSEQ - t) : (t - 1);
            g_lstm_out[(size_t)tprev * 512 + dir * 256 + rank * 32 + lane] = hprev;
        }
        __syncthreads();      // part[p] ready; all local reads of hb[p] retired

        if (tid < 32) {
            const int jj = tid;
            float gv[4];
#pragma unroll
            for (int gg = 0; gg < 4; gg++) {
                float s = part[p][0][gg * 32 + jj] + part[p][1][gg * 32 + jj]
                        + part[p][2][gg * 32 + jj] + part[p][3][gg * 32 + jj];
                gv[gg] = xpv[gg] + s;
            }
            float ii  = fsig(gv[0]);
            float ff  = fsig(gv[1]);
            float ggt = ftanh_(gv[2]);
            float oo  = fsig(gv[3]);
            c = ff * c + ii * ggt;
            hj = oo * ftanh_(c);

            if (t + 1 < LSEQ) {
                // (1) sends via precomputed windows + compile-time offsets:
                // hb[1] = hb[0] + 1024 bytes; fb1 = fb0 + 8 bytes
                if (p == 0) {
#pragma unroll
                    for (int pc = 0; pc < 8; pc++)
                        st_async_tx(slot0[pc] + 1024, hj, bar0[pc] + 8);
                } else {
#pragma unroll
                    for (int pc = 0; pc < 8; pc++)
                        st_async_tx(slot0[pc], hj, bar0[pc]);
                }
            }
#pragma unroll
            for (int gg = 0; gg < 4; gg++) xpv[gg] = xpn[gg];
        }
        // no second __syncthreads: part is double-buffered by p; reuse of part[p]
        // at t+2 is ordered through two full-barrier generations.
        p ^= 1;
    }

    // final timestep's output (warp 1 covered t-1 only up to LSEQ-2)
    if (tid < 32) {
        int tt = dir ? 0 : (LSEQ - 1);
        g_lstm_out[(size_t)tt * 512 + dir * 256 + rank * 32 + tid] = hj;
    }
}

// ---------------- kernel 3: feats = lstm_out @ W_out^T + b_out ----------------
__global__ __launch_bounds__(256, 4)
void feats_kernel(const float* __restrict__ Wout, const float* __restrict__ bout)
{
    int gw   = (blockIdx.x * blockDim.x + threadIdx.x) >> 5;
    int lane = threadIdx.x & 31;
    if (gw >= LSEQ * NT) return;
    int t = gw / NT, n = gw % NT;

    const float4* xr = (const float4*)(g_lstm_out + (size_t)t * 512);
    const float4* wr = (const float4*)(Wout + (size_t)n * 512);
    float acc = 0.0f;
#pragma unroll
    for (int q = 0; q < 4; q++) {
        float4 a = xr[q * 32 + lane];
        float4 b = __ldg(&wr[q * 32 + lane]);
        acc += a.x * b.x + a.y * b.y + a.z * b.z + a.w * b.w;
    }
#pragma unroll
    for (int off = 16; off; off >>= 1)
        acc += __shfl_down_sync(0xffffffffu, acc, off);
    if (lane == 0) g_feats[t * NT + n] = acc + bout[n];
}

// ---------------- kernel 4: Viterbi (R10 version — measured best) ----------------
#define BP_BYTES   (LSEQ * NT)               // 98304
#define FCH_BYTES  (256 * NT * 4)            // 24576
#define PATH_BYTES (LSEQ * 4)                // 16384
#define VSMEM      (BP_BYTES + FCH_BYTES + PATH_BYTES + 128)

// combine keeping 'a' (lower index range) on ties -> jnp.argmax first-max
__device__ __forceinline__ void amax2_(float& v, int& i, float v2, int i2) {
    bool ge = (v >= v2);
    v = ge ? v : v2;
    i = ge ? i : i2;
}

__global__ void viterbi_kernel(const float* __restrict__ trans,
                               float* __restrict__ out, int out_size)
{
    extern __shared__ char sm[];
    unsigned char* bp   = (unsigned char*)sm;
    float*         fch  = (float*)(sm + BP_BYTES);
    int*           path = (int*)(sm + BP_BYTES + FCH_BYTES);
    __shared__ float score_s;

    const int tid = threadIdx.x;

    float fvr = (tid == START_TAG) ? 0.0f : NEGINF;
    float trow[NT];
    if (tid < NT) {
#pragma unroll
        for (int p_ = 0; p_ < NT; p_++) trow[p_] = trans[tid * NT + p_];
    } else {
#pragma unroll
        for (int p_ = 0; p_ < NT; p_++) trow[p_] = 0.0f;
    }
    __syncthreads();

    for (int ch = 0; ch < LSEQ / 256; ch++) {
        const float* src = g_feats + (size_t)ch * 256 * NT;
        for (int i = tid; i < 256 * NT; i += blockDim.x) fch[i] = src[i];
        __syncthreads();

        if (tid < 32) {
            for (int s = 0; s < 256; s++) {
                int t = ch * 256 + s;
                float sc[32];
#pragma unroll
                for (int k = 0; k < NT; k++)
                    sc[k] = __shfl_sync(0xffffffffu, fvr, k) + trow[k];
#pragma unroll
                for (int k = NT; k < 32; k++) sc[k] = -3.4e38f;

                float v[16]; int ix[16];
#pragma unroll
                for (int m = 0; m < 16; m++) {
                    bool ge = (sc[2 * m] >= sc[2 * m + 1]);
                    v[m]  = ge ? sc[2 * m] : sc[2 * m + 1];
                    ix[m] = ge ? (2 * m) : (2 * m + 1);
                }
#pragma unroll
                for (int m = 0; m < 8; m++) amax2_(v[m], ix[m], v[m + 8], ix[m + 8]);
#pragma unroll
                for (int m = 0; m < 4; m++) amax2_(v[m], ix[m], v[m + 4], ix[m + 4]);
#pragma unroll
                for (int m = 0; m < 2; m++) amax2_(v[m], ix[m], v[m + 2], ix[m + 2]);
                amax2_(v[0], ix[0], v[1], ix[1]);

                float fval = (tid < NT) ? fch[s * NT + tid] : 0.0f;
                fvr = v[0] + fval;
                if (tid < NT) bp[t * NT + tid] = (unsigned char)ix[0];
            }
        }
        __syncthreads();
    }

    if (tid < 32) {
        float sc[32];
#pragma unroll
        for (int k = 0; k < NT; k++)
            sc[k] = __shfl_sync(0xffffffffu, fvr, k) + __ldg(&trans[STOP_TAG * NT + k]);
#pragma unroll
        for (int k = NT; k < 32; k++) sc[k] = -3.4e38f;
        float v[16]; int ix[16];
#pragma unroll
        for (int m = 0; m < 16; m++) {
            bool ge = (sc[2 * m] >= sc[2 * m + 1]);
            v[m]  = ge ? sc[2 * m] : sc[2 * m + 1];
            ix[m] = ge ? (2 * m) : (2 * m + 1);
        }
#pragma unroll
        for (int m = 0; m < 8; m++) amax2_(v[m], ix[m], v[m + 8], ix[m + 8]);
#pragma unroll
        for (int m = 0; m < 4; m++) amax2_(v[m], ix[m], v[m + 4], ix[m + 4]);
#pragma unroll
        for (int m = 0; m < 2; m++) amax2_(v[m], ix[m], v[m + 2], ix[m + 2]);
        amax2_(v[0], ix[0], v[1], ix[1]);

        if (tid == 0) {
            score_s = v[0];
            int tag = ix[0];
            for (int t = LSEQ - 1; t >= 0; t--) {
                path[t] = tag;
                tag = bp[t * NT + tag];
            }
        }
    }
    __syncthreads();

    if (out_size >= LSEQ + 1) {
        if (tid == 0) out[0] = score_s;
        for (int t = tid; t < LSEQ; t += blockDim.x) out[1 + t] = (float)path[t];
    } else if (out_size >= LSEQ) {
        for (int t = tid; t < LSEQ; t += blockDim.x) out[t] = (float)path[t];
    } else if (out_size >= 1) {
        if (tid == 0) out[0] = score_s;
    }
}

// ---------------- launch ----------------
extern "C" void kernel_launch(void* const* d_in, const int* in_sizes, int n_in,
                              void* d_out, int out_size)
{
    const int*   sent  = (const int*)d_in[0];
    const float* h0    = (const float*)d_in[1];
    const float* c0    = (const float*)d_in[2];
    const float* emb   = (const float*)d_in[3];
    const float* Wihf  = (const float*)d_in[4];
    const float* Whhf  = (const float*)d_in[5];
    const float* bihf  = (const float*)d_in[6];
    const float* bhhf  = (const float*)d_in[7];
    const float* Wihb  = (const float*)d_in[8];
    const float* Whhb  = (const float*)d_in[9];
    const float* bihb  = (const float*)d_in[10];
    const float* bhhb  = (const float*)d_in[11];
    const float* Wout  = (const float*)d_in[12];
    const float* bout  = (const float*)d_in[13];
    const float* trans = (const float*)d_in[14];

    cudaFuncSetAttribute(viterbi_kernel,
                         cudaFuncAttributeMaxDynamicSharedMemorySize, VSMEM);

    proj_kernel<<<dim3(LSEQ / 8, 2), 1024>>>(sent, emb, Wihf, bihf, bhhf,
                                             Wihb, bihb, bhhb);
    lstm_kernel<<<16, 512>>>(h0, c0, Whhf, Whhb);

    int nwarps  = LSEQ * NT;
    int nblocks = (nwarps * 32 + 255) / 256;
    feats_kernel<<<nblocks, 256>>>(Wout, bout);

    viterbi_kernel<<<1, 128, VSMEM>>>(trans, (float*)d_out, out_size);
}